// round 6
// baseline (speedup 1.0000x reference)
#include <cuda_runtime.h>

#define NP     19000
#define E_SG   1500000
#define N_SG   800000
#define ND     1024
#define B_DD   4096
#define NB     148
#define NT     1024
#define NWARP  32
#define CHUNK  129          // ceil(NP/NB)
#define ASTR   264          // A tile row stride (floats), 256 + 8 pad
#define NTILE  297          // ceil(19000/64)

// ---------------- persistent device state (no allocation allowed) -----------
__device__ float    g_h1[NP * 256];
__device__ float    g_h2[NP * 256];
__device__ float    g_dinv[NP];
__device__ int      g_deg[NP];           // zero at entry; re-zeroed each run
__device__ int      g_rowstart[NP + 1];
__device__ int      g_fill[NP];
__device__ int      g_csr_src[E_SG];
__device__ float    g_drug[ND * 256];
__device__ int      g_drug_start[ND + 1];
__device__ int      g_part[NB];
__device__ int      g_poff[NB];
__device__ int      g_tctr[2];           // work-stealing tile counters (layer 0/1)
__device__ unsigned g_cnt;               // barrier arrival counter (self-resetting)
__device__ unsigned g_gen;               // barrier generation (monotone forever)

// Software grid barrier; all 148 blocks co-resident (1 block/SM: 84KB smem, 64 regs).
__device__ __forceinline__ void gridbar(unsigned gen0, unsigned k) {
    __syncthreads();
    if (threadIdx.x == 0) {
        __threadfence();
        unsigned pos = atomicAdd(&g_cnt, 1u);
        if (pos == NB - 1u) {
            atomicExch(&g_cnt, 0u);
            __threadfence();
            atomicAdd(&g_gen, 1u);
        } else {
            unsigned target = gen0 + k;
            while ((int)(*(volatile unsigned*)&g_gen - target) < 0) __nanosleep(64);
        }
        __threadfence();
    }
    __syncthreads();
}

// ---------------- fused GCN layer: agg (warp-per-row) + GEMM in smem --------
// Column mapping per lane: block0 = cols [lane*4, +4), block1 = cols [128+lane*4, +4)
__device__ void layer_phase(const float4* __restrict__ in, const float* __restrict__ W,
                            const float* __restrict__ bias, const float4* __restrict__ resid,
                            float4* __restrict__ out, bool relu, int layer,
                            float* A, float* Bs, int* s_tile) {
    const int tid  = threadIdx.x;
    const int lane = tid & 31;
    const int wid  = tid >> 5;           // 0..31

    for (;;) {
        __syncthreads();
        if (tid == 0) *s_tile = atomicAdd(&g_tctr[layer], 1);
        __syncthreads();
        const int tile = *s_tile;
        if (tile >= NTILE) break;
        const int r0 = tile * 64;

        // ---- gather: warp wid produces rows wid*2, wid*2+1 ----
        for (int i = 0; i < 2; i++) {
            int rr = wid * 2 + i;
            int r  = r0 + rr;
            float4 a0 = make_float4(0.f, 0.f, 0.f, 0.f);
            float4 a1 = make_float4(0.f, 0.f, 0.f, 0.f);
            if (r < NP) {
                int beg = g_rowstart[r];
                int end = g_rowstart[r + 1];
                for (int base = beg; base < end; base += 32) {
                    int m = min(32, end - base);
                    int sidx = 0; float sw = 0.f;
                    if (lane < m) {
                        int s = g_csr_src[base + lane];
                        sidx = s * 64;
                        sw   = g_dinv[s];
                    }
                    int k = 0;
                    for (; k + 2 <= m; k += 2) {
                        int   i0 = __shfl_sync(0xffffffffu, sidx, k);
                        float w0 = __shfl_sync(0xffffffffu, sw,   k);
                        int   i1 = __shfl_sync(0xffffffffu, sidx, k + 1);
                        float w1 = __shfl_sync(0xffffffffu, sw,   k + 1);
                        float4 p0 = in[i0 + lane];
                        float4 p1 = in[i0 + 32 + lane];
                        float4 q0 = in[i1 + lane];
                        float4 q1 = in[i1 + 32 + lane];
                        a0.x = fmaf(p0.x, w0, a0.x); a0.y = fmaf(p0.y, w0, a0.y);
                        a0.z = fmaf(p0.z, w0, a0.z); a0.w = fmaf(p0.w, w0, a0.w);
                        a1.x = fmaf(p1.x, w0, a1.x); a1.y = fmaf(p1.y, w0, a1.y);
                        a1.z = fmaf(p1.z, w0, a1.z); a1.w = fmaf(p1.w, w0, a1.w);
                        a0.x = fmaf(q0.x, w1, a0.x); a0.y = fmaf(q0.y, w1, a0.y);
                        a0.z = fmaf(q0.z, w1, a0.z); a0.w = fmaf(q0.w, w1, a0.w);
                        a1.x = fmaf(q1.x, w1, a1.x); a1.y = fmaf(q1.y, w1, a1.y);
                        a1.z = fmaf(q1.z, w1, a1.z); a1.w = fmaf(q1.w, w1, a1.w);
                    }
                    if (k < m) {
                        int   i0 = __shfl_sync(0xffffffffu, sidx, k);
                        float w0 = __shfl_sync(0xffffffffu, sw,   k);
                        float4 p0 = in[i0 + lane];
                        float4 p1 = in[i0 + 32 + lane];
                        a0.x = fmaf(p0.x, w0, a0.x); a0.y = fmaf(p0.y, w0, a0.y);
                        a0.z = fmaf(p0.z, w0, a0.z); a0.w = fmaf(p0.w, w0, a0.w);
                        a1.x = fmaf(p1.x, w0, a1.x); a1.y = fmaf(p1.y, w0, a1.y);
                        a1.z = fmaf(p1.z, w0, a1.z); a1.w = fmaf(p1.w, w0, a1.w);
                    }
                }
                float di = g_dinv[r];
                float4 s0 = in[r * 64 + lane];
                float4 s1 = in[r * 64 + 32 + lane];
                a0.x = (a0.x + s0.x * di) * di; a0.y = (a0.y + s0.y * di) * di;
                a0.z = (a0.z + s0.z * di) * di; a0.w = (a0.w + s0.w * di) * di;
                a1.x = (a1.x + s1.x * di) * di; a1.y = (a1.y + s1.y * di) * di;
                a1.z = (a1.z + s1.z * di) * di; a1.w = (a1.w + s1.w * di) * di;
            }
            *(float4*)&A[rr * ASTR + lane * 4]       = a0;
            *(float4*)&A[rr * ASTR + 128 + lane * 4] = a1;
        }
        __syncthreads();

        // ---- GEMM: H[64,256] = A[64,256] * W[256,256] ----
        float acc[2][8];
        #pragma unroll
        for (int i = 0; i < 2; i++)
            #pragma unroll
            for (int j = 0; j < 8; j++) acc[i][j] = 0.f;

        for (int k0 = 0; k0 < 256; k0 += 16) {
            {
                int br = tid >> 6;             // 0..15
                int bc = (tid & 63) * 4;       // 0..252
                *(float4*)&Bs[br * 256 + bc] = *(const float4*)&W[(k0 + br) * 256 + bc];
            }
            __syncthreads();
            #pragma unroll
            for (int k = 0; k < 16; k++) {
                float a0 = A[(wid * 2 + 0) * ASTR + k0 + k];
                float a1 = A[(wid * 2 + 1) * ASTR + k0 + k];
                float4 b0 = *(float4*)&Bs[k * 256 + lane * 4];
                float4 b1 = *(float4*)&Bs[k * 256 + 128 + lane * 4];
                acc[0][0] = fmaf(a0, b0.x, acc[0][0]);
                acc[0][1] = fmaf(a0, b0.y, acc[0][1]);
                acc[0][2] = fmaf(a0, b0.z, acc[0][2]);
                acc[0][3] = fmaf(a0, b0.w, acc[0][3]);
                acc[0][4] = fmaf(a0, b1.x, acc[0][4]);
                acc[0][5] = fmaf(a0, b1.y, acc[0][5]);
                acc[0][6] = fmaf(a0, b1.z, acc[0][6]);
                acc[0][7] = fmaf(a0, b1.w, acc[0][7]);
                acc[1][0] = fmaf(a1, b0.x, acc[1][0]);
                acc[1][1] = fmaf(a1, b0.y, acc[1][1]);
                acc[1][2] = fmaf(a1, b0.z, acc[1][2]);
                acc[1][3] = fmaf(a1, b0.w, acc[1][3]);
                acc[1][4] = fmaf(a1, b1.x, acc[1][4]);
                acc[1][5] = fmaf(a1, b1.y, acc[1][5]);
                acc[1][6] = fmaf(a1, b1.z, acc[1][6]);
                acc[1][7] = fmaf(a1, b1.w, acc[1][7]);
            }
            __syncthreads();
        }

        // ---- epilogue: bias (+residual) (+relu) -> out ----
        float4 bi0 = *(const float4*)&bias[lane * 4];
        float4 bi1 = *(const float4*)&bias[128 + lane * 4];
        #pragma unroll
        for (int i = 0; i < 2; i++) {
            int r = r0 + wid * 2 + i;
            if (r < NP) {
                float4 o0 = make_float4(acc[i][0] + bi0.x, acc[i][1] + bi0.y,
                                        acc[i][2] + bi0.z, acc[i][3] + bi0.w);
                float4 o1 = make_float4(acc[i][4] + bi1.x, acc[i][5] + bi1.y,
                                        acc[i][6] + bi1.z, acc[i][7] + bi1.w);
                if (resid) {
                    float4 r4 = resid[r * 64 + lane];
                    float4 r5 = resid[r * 64 + 32 + lane];
                    o0.x += r4.x; o0.y += r4.y; o0.z += r4.z; o0.w += r4.w;
                    o1.x += r5.x; o1.y += r5.y; o1.z += r5.z; o1.w += r5.w;
                }
                if (relu) {
                    o0.x = fmaxf(o0.x, 0.f); o0.y = fmaxf(o0.y, 0.f);
                    o0.z = fmaxf(o0.z, 0.f); o0.w = fmaxf(o0.w, 0.f);
                    o1.x = fmaxf(o1.x, 0.f); o1.y = fmaxf(o1.y, 0.f);
                    o1.z = fmaxf(o1.z, 0.f); o1.w = fmaxf(o1.w, 0.f);
                }
                out[r * 64 + lane]      = o0;
                out[r * 64 + 32 + lane] = o1;
            }
        }
    }
}

// ---------------- the single mega-kernel ------------------------------------
__global__ __launch_bounds__(NT, 1) void mega_kernel(
    const float* __restrict__ x, const int* __restrict__ ddb,
    const int* __restrict__ src, const int* __restrict__ dst,
    const int* __restrict__ nodes, const int* __restrict__ avgix,
    const float* __restrict__ W1, const float* __restrict__ b1,
    const float* __restrict__ W2, const float* __restrict__ b2,
    float* __restrict__ out)
{
    extern __shared__ float smem[];
    float* A  = smem;                  // 64 * 264 floats
    float* Bs = smem + 64 * ASTR;      // 16 * 256 floats
    __shared__ unsigned s_gen0;
    __shared__ int s_tile;

    const int tid  = threadIdx.x;
    const int lane = tid & 31;
    const int wid  = tid >> 5;
    const int gtid = blockIdx.x * NT + tid;
    const int gs   = NB * NT;

    if (tid == 0) s_gen0 = *(volatile unsigned*)&g_gen;
    __syncthreads();
    const unsigned gen0 = s_gen0;

    // ---- P0: degree histogram + drug boundaries + counter reset ----
    for (int e = gtid; e < E_SG; e += gs)
        atomicAdd(&g_deg[dst[e]], 1);
    if (gtid < 2) g_tctr[gtid] = 0;
    if (gtid <= ND) {
        if (gtid == ND) g_drug_start[ND] = N_SG;
        else {
            int lo = 0, hi = N_SG;
            while (lo < hi) {
                int mid = (lo + hi) >> 1;
                if (avgix[mid] < gtid) lo = mid + 1; else hi = mid;
            }
            g_drug_start[gtid] = lo;
        }
    }
    gridbar(gen0, 1);

    // ---- P1a: per-block chunk sums ----
    int* si = (int*)A;
    {
        int n0  = blockIdx.x * CHUNK;
        int len = NP - n0; if (len > CHUNK) len = CHUNK; if (len < 0) len = 0;
        int v = (tid < len) ? g_deg[n0 + tid] : 0;
        if (tid < CHUNK) si[tid] = v;
        __syncthreads();
        if (tid == 0) {
            int s = 0;
            for (int i = 0; i < len; i++) s += si[i];
            g_part[blockIdx.x] = s;
        }
    }
    gridbar(gen0, 2);

    // ---- P1b: block 0 scans the 148 partials ----
    if (blockIdx.x == 0) {
        int pv = (tid < NB) ? g_part[tid] : 0;
        if (tid < NB) si[tid] = pv;
        __syncthreads();
        if (tid == 0) {
            int run = 0;
            for (int i = 0; i < NB; i++) { int t = si[i]; si[i] = run; run += t; }
        }
        __syncthreads();
        if (tid < NB) g_poff[tid] = si[tid];
    }
    gridbar(gen0, 3);

    // ---- P1c: per-chunk prefix -> rowstart/fill/dinv ----
    {
        int n0  = blockIdx.x * CHUNK;
        int len = NP - n0; if (len > CHUNK) len = CHUNK; if (len < 0) len = 0;
        int v = (tid < len) ? g_deg[n0 + tid] : 0;
        if (tid < CHUNK) si[tid] = v;
        __syncthreads();
        if (tid == 0) {
            int run = g_poff[blockIdx.x];
            for (int i = 0; i < len; i++) { int t = si[i]; si[i] = run; run += t; }
        }
        __syncthreads();
        if (tid < len) {
            int node = n0 + tid;
            int rs = si[tid];
            g_rowstart[node] = rs;
            g_fill[node]     = rs;
            g_dinv[node]     = rsqrtf((float)v + 1.0f);
        }
        if (blockIdx.x == 0 && tid == 0) g_rowstart[NP] = E_SG;
    }
    gridbar(gen0, 4);

    // ---- P2: CSR fill + reset g_deg for next replay ----
    for (int e = gtid; e < E_SG; e += gs) {
        int d   = dst[e];
        int pos = atomicAdd(&g_fill[d], 1);
        g_csr_src[pos] = src[e];
    }
    for (int i = gtid; i < NP; i += gs) g_deg[i] = 0;
    gridbar(gen0, 5);

    // ---- P3: layer 1  h1 = relu(agg(x) @ W1 + b1) ----
    layer_phase((const float4*)x, W1, b1, nullptr, (float4*)g_h1, true, 0, A, Bs, &s_tile);
    gridbar(gen0, 6);

    // ---- P4: layer 2  h2 = agg(h1) @ W2 + b2 + h1 ----
    layer_phase((const float4*)g_h1, W2, b2, (const float4*)g_h1, (float4*)g_h2, false, 1,
                A, Bs, &s_tile);
    gridbar(gen0, 7);

    // ---- P5: scatter-mean pooling (32 warps gather, smem reduce) ----
    {
        const float4* h2 = (const float4*)g_h2;
        for (int d = blockIdx.x; d < ND; d += NB) {
            int beg = g_drug_start[d];
            int end = g_drug_start[d + 1];
            float4 a0 = make_float4(0.f, 0.f, 0.f, 0.f);
            float4 a1 = make_float4(0.f, 0.f, 0.f, 0.f);
            for (int base = beg + wid * 32; base < end; base += NT) {
                int m = min(32, end - base);
                int nidx = 0;
                if (lane < m) nidx = nodes[base + lane] * 64;
                int k = 0;
                for (; k + 2 <= m; k += 2) {
                    int i0 = __shfl_sync(0xffffffffu, nidx, k);
                    int i1 = __shfl_sync(0xffffffffu, nidx, k + 1);
                    float4 p0 = h2[i0 + lane];
                    float4 p1 = h2[i0 + 32 + lane];
                    float4 q0 = h2[i1 + lane];
                    float4 q1 = h2[i1 + 32 + lane];
                    a0.x += p0.x + q0.x; a0.y += p0.y + q0.y;
                    a0.z += p0.z + q0.z; a0.w += p0.w + q0.w;
                    a1.x += p1.x + q1.x; a1.y += p1.y + q1.y;
                    a1.z += p1.z + q1.z; a1.w += p1.w + q1.w;
                }
                if (k < m) {
                    int i0 = __shfl_sync(0xffffffffu, nidx, k);
                    float4 p0 = h2[i0 + lane];
                    float4 p1 = h2[i0 + 32 + lane];
                    a0.x += p0.x; a0.y += p0.y; a0.z += p0.z; a0.w += p0.w;
                    a1.x += p1.x; a1.y += p1.y; a1.z += p1.z; a1.w += p1.w;
                }
            }
            __syncthreads();
            float* P = A;   // 32 warps x 256 floats = 32KB
            *(float4*)&P[wid * 256 + lane * 4]       = a0;
            *(float4*)&P[wid * 256 + 128 + lane * 4] = a1;
            __syncthreads();
            if (tid < 256) {
                float s = 0.f;
                #pragma unroll
                for (int w = 0; w < NWARP; w++) s += P[w * 256 + tid];
                float inv = 1.0f / fmaxf((float)(end - beg), 1.0f);
                g_drug[d * 256 + tid] = s * inv;
            }
            __syncthreads();
        }
    }
    gridbar(gen0, 8);

    // ---- P6: prediction head ----
    {
        const float4* gd = (const float4*)g_drug;
        for (int p = blockIdx.x * NWARP + wid; p < B_DD; p += NB * NWARP) {
            int a = ddb[p];
            int b = ddb[B_DD + p];
            float4 va0 = gd[a * 64 + lane], va1 = gd[a * 64 + 32 + lane];
            float4 vb0 = gd[b * 64 + lane], vb1 = gd[b * 64 + 32 + lane];
            float s = va0.x * vb0.x + va0.y * vb0.y + va0.z * vb0.z + va0.w * vb0.w
                    + va1.x * vb1.x + va1.y * vb1.y + va1.z * vb1.z + va1.w * vb1.w;
            #pragma unroll
            for (int off = 16; off; off >>= 1)
                s += __shfl_down_sync(0xffffffffu, s, off);
            if (lane == 0) out[p] = s;
        }
    }
}

// ---------------- launch ----------------------------------------------------
extern "C" void kernel_launch(void* const* d_in, const int* in_sizes, int n_in,
                              void* d_out, int out_size) {
    const float* x     = (const float*)d_in[0];
    const int*   ddb   = (const int*)d_in[1];
    const int*   sg_ei = (const int*)d_in[4];
    const int*   nodes = (const int*)d_in[5];
    const int*   avgix = (const int*)d_in[6];
    const float* W1    = (const float*)d_in[7];
    const float* b1    = (const float*)d_in[8];
    const float* W2    = (const float*)d_in[9];
    const float* b2    = (const float*)d_in[10];
    float* out = (float*)d_out;

    const int smem_bytes = (64 * ASTR + 16 * 256) * (int)sizeof(float);  // 83968
    static bool attr_set = false;
    if (!attr_set) {
        cudaFuncSetAttribute(mega_kernel, cudaFuncAttributeMaxDynamicSharedMemorySize,
                             smem_bytes);
        attr_set = true;
    }

    mega_kernel<<<NB, NT, smem_bytes>>>(x, ddb, sg_ei, sg_ei + E_SG,
                                        nodes, avgix, W1, b1, W2, b2, out);
}

// round 7
// speedup vs baseline: 1.0698x; 1.0698x over previous
#include <cuda_runtime.h>
#include <cuda_bf16.h>

#define NP     19000
#define E_SG   1500000
#define N_SG   800000
#define ND     1024
#define B_DD   4096
#define NB     148
#define NT     512
#define NWARP  16
#define CHUNK  129          // ceil(NP/NB)
#define ASTR   264          // A tile row stride (floats), 256 + 8 pad
#define NTILE  297          // ceil(19000/64)

// ---------------- persistent device state (no allocation allowed) -----------
__device__ float    g_h1[NP * 256];          // fp32 h1 (residual + GEMM source of truth)
__device__ unsigned g_xb [NP * 128];         // x  in bf16x2
__device__ unsigned g_h1b[NP * 128];         // h1 in bf16x2 (gather input, layer 2)
__device__ unsigned g_h2b[NP * 128];         // h2 in bf16x2 (pool input)
__device__ float    g_dinv[NP];
__device__ int      g_deg[NP];               // zero at entry; re-zeroed each run
__device__ int      g_rowstart[NP + 1];
__device__ int      g_fill[NP];
__device__ int      g_csr_src[E_SG];
__device__ float    g_drug[ND * 256];
__device__ int      g_drug_start[ND + 1];
__device__ int      g_part[NB];
__device__ int      g_poff[NB];
__device__ int      g_tctr[2];
__device__ unsigned g_cnt;
__device__ unsigned g_gen;

__device__ __forceinline__ unsigned pack2(float a, float b) {
    __nv_bfloat162 t = __floats2bfloat162_rn(a, b);
    return *(unsigned*)&t;
}
__device__ __forceinline__ float2 unpack2(unsigned u) {
    return __bfloat1622float2(*(__nv_bfloat162*)&u);
}

// Software grid barrier; all 148 blocks co-resident (1 block/SM).
__device__ __forceinline__ void gridbar(unsigned gen0, unsigned k) {
    __syncthreads();
    if (threadIdx.x == 0) {
        __threadfence();
        unsigned pos = atomicAdd(&g_cnt, 1u);
        if (pos == NB - 1u) {
            atomicExch(&g_cnt, 0u);
            __threadfence();
            atomicAdd(&g_gen, 1u);
        } else {
            unsigned target = gen0 + k;
            while ((int)(*(volatile unsigned*)&g_gen - target) < 0) __nanosleep(64);
        }
        __threadfence();
    }
    __syncthreads();
}

// accumulate one bf16 row (uint4 = 8 bf16 at cols lane*8..+7) * w into a[8]
__device__ __forceinline__ void acc_row(float* a, uint4 u, float w) {
    float2 f;
    f = unpack2(u.x); a[0] = fmaf(f.x, w, a[0]); a[1] = fmaf(f.y, w, a[1]);
    f = unpack2(u.y); a[2] = fmaf(f.x, w, a[2]); a[3] = fmaf(f.y, w, a[3]);
    f = unpack2(u.z); a[4] = fmaf(f.x, w, a[4]); a[5] = fmaf(f.y, w, a[5]);
    f = unpack2(u.w); a[6] = fmaf(f.x, w, a[6]); a[7] = fmaf(f.y, w, a[7]);
}

// ---------------- fused GCN layer: bf16 gather + fp32 GEMM in smem ----------
// hb_out may be null (layer writes bf16 mirror only when needed)
__device__ void layer_phase(const uint4* __restrict__ inb, const float* __restrict__ W,
                            const float* __restrict__ bias, const float4* __restrict__ resid,
                            float4* __restrict__ out_f32, uint2* __restrict__ out_b16,
                            bool relu, int layer,
                            float* A, float* Bs, int* s_tile) {
    const int tid  = threadIdx.x;
    const int lane = tid & 31;
    const int wid  = tid >> 5;           // 0..15

    for (;;) {
        __syncthreads();
        if (tid == 0) *s_tile = atomicAdd(&g_tctr[layer], 1);
        __syncthreads();
        const int tile = *s_tile;
        if (tile >= NTILE) break;
        const int r0 = tile * 64;

        // ---- gather: warp wid produces rows wid*4 .. wid*4+3 (cols lane*8..+7)
        for (int i = 0; i < 4; i++) {
            int rr = wid * 4 + i;
            int r  = r0 + rr;
            float a[8] = {0.f, 0.f, 0.f, 0.f, 0.f, 0.f, 0.f, 0.f};
            if (r < NP) {
                int beg = g_rowstart[r];
                int end = g_rowstart[r + 1];
                for (int base = beg; base < end; base += 32) {
                    int m = min(32, end - base);
                    int sidx = 0; float sw = 0.f;
                    if (lane < m) {
                        int s = g_csr_src[base + lane];
                        sidx = s * 32;
                        sw   = g_dinv[s];
                    }
                    int k = 0;
                    for (; k + 4 <= m; k += 4) {
                        int   i0 = __shfl_sync(0xffffffffu, sidx, k);
                        float w0 = __shfl_sync(0xffffffffu, sw,   k);
                        int   i1 = __shfl_sync(0xffffffffu, sidx, k + 1);
                        float w1 = __shfl_sync(0xffffffffu, sw,   k + 1);
                        int   i2 = __shfl_sync(0xffffffffu, sidx, k + 2);
                        float w2 = __shfl_sync(0xffffffffu, sw,   k + 2);
                        int   i3 = __shfl_sync(0xffffffffu, sidx, k + 3);
                        float w3 = __shfl_sync(0xffffffffu, sw,   k + 3);
                        uint4 u0 = inb[i0 + lane];
                        uint4 u1 = inb[i1 + lane];
                        uint4 u2 = inb[i2 + lane];
                        uint4 u3 = inb[i3 + lane];
                        acc_row(a, u0, w0);
                        acc_row(a, u1, w1);
                        acc_row(a, u2, w2);
                        acc_row(a, u3, w3);
                    }
                    for (; k < m; k++) {
                        int   i0 = __shfl_sync(0xffffffffu, sidx, k);
                        float w0 = __shfl_sync(0xffffffffu, sw,   k);
                        uint4 u0 = inb[i0 + lane];
                        acc_row(a, u0, w0);
                    }
                }
                float di = g_dinv[r];
                uint4 us = inb[r * 32 + lane];
                float2 f;
                f = unpack2(us.x); a[0] = (a[0] + f.x * di) * di; a[1] = (a[1] + f.y * di) * di;
                f = unpack2(us.y); a[2] = (a[2] + f.x * di) * di; a[3] = (a[3] + f.y * di) * di;
                f = unpack2(us.z); a[4] = (a[4] + f.x * di) * di; a[5] = (a[5] + f.y * di) * di;
                f = unpack2(us.w); a[6] = (a[6] + f.x * di) * di; a[7] = (a[7] + f.y * di) * di;
            }
            *(float4*)&A[rr * ASTR + lane * 8]     = make_float4(a[0], a[1], a[2], a[3]);
            *(float4*)&A[rr * ASTR + lane * 8 + 4] = make_float4(a[4], a[5], a[6], a[7]);
        }
        __syncthreads();

        // ---- GEMM: H[64,256] = A[64,256] * W[256,256] ----
        // output cols per thread: [lane*4, +4) and [128+lane*4, +4)
        float acc[4][8];
        #pragma unroll
        for (int i = 0; i < 4; i++)
            #pragma unroll
            for (int j = 0; j < 8; j++) acc[i][j] = 0.f;

        for (int k0 = 0; k0 < 256; k0 += 16) {
            #pragma unroll
            for (int q = 0; q < 2; q++) {
                int l  = tid + 512 * q;
                int br = l >> 6;
                int bc = (l & 63) * 4;
                *(float4*)&Bs[br * 256 + bc] = *(const float4*)&W[(k0 + br) * 256 + bc];
            }
            __syncthreads();
            #pragma unroll
            for (int k = 0; k < 16; k++) {
                float a[4];
                #pragma unroll
                for (int i = 0; i < 4; i++) a[i] = A[(wid * 4 + i) * ASTR + k0 + k];
                float4 b0 = *(float4*)&Bs[k * 256 + lane * 4];
                float4 b1 = *(float4*)&Bs[k * 256 + 128 + lane * 4];
                #pragma unroll
                for (int i = 0; i < 4; i++) {
                    acc[i][0] = fmaf(a[i], b0.x, acc[i][0]);
                    acc[i][1] = fmaf(a[i], b0.y, acc[i][1]);
                    acc[i][2] = fmaf(a[i], b0.z, acc[i][2]);
                    acc[i][3] = fmaf(a[i], b0.w, acc[i][3]);
                    acc[i][4] = fmaf(a[i], b1.x, acc[i][4]);
                    acc[i][5] = fmaf(a[i], b1.y, acc[i][5]);
                    acc[i][6] = fmaf(a[i], b1.z, acc[i][6]);
                    acc[i][7] = fmaf(a[i], b1.w, acc[i][7]);
                }
            }
            __syncthreads();
        }

        // ---- epilogue: bias (+residual) (+relu) -> fp32 and/or bf16 ----
        float4 bi0 = *(const float4*)&bias[lane * 4];
        float4 bi1 = *(const float4*)&bias[128 + lane * 4];
        #pragma unroll
        for (int i = 0; i < 4; i++) {
            int r = r0 + wid * 4 + i;
            if (r < NP) {
                float4 o0 = make_float4(acc[i][0] + bi0.x, acc[i][1] + bi0.y,
                                        acc[i][2] + bi0.z, acc[i][3] + bi0.w);
                float4 o1 = make_float4(acc[i][4] + bi1.x, acc[i][5] + bi1.y,
                                        acc[i][6] + bi1.z, acc[i][7] + bi1.w);
                if (resid) {
                    float4 r4 = resid[r * 64 + lane];
                    float4 r5 = resid[r * 64 + 32 + lane];
                    o0.x += r4.x; o0.y += r4.y; o0.z += r4.z; o0.w += r4.w;
                    o1.x += r5.x; o1.y += r5.y; o1.z += r5.z; o1.w += r5.w;
                }
                if (relu) {
                    o0.x = fmaxf(o0.x, 0.f); o0.y = fmaxf(o0.y, 0.f);
                    o0.z = fmaxf(o0.z, 0.f); o0.w = fmaxf(o0.w, 0.f);
                    o1.x = fmaxf(o1.x, 0.f); o1.y = fmaxf(o1.y, 0.f);
                    o1.z = fmaxf(o1.z, 0.f); o1.w = fmaxf(o1.w, 0.f);
                }
                if (out_f32) {
                    out_f32[r * 64 + lane]      = o0;
                    out_f32[r * 64 + 32 + lane] = o1;
                }
                if (out_b16) {
                    uint2 p0, p1;
                    p0.x = pack2(o0.x, o0.y); p0.y = pack2(o0.z, o0.w);
                    p1.x = pack2(o1.x, o1.y); p1.y = pack2(o1.z, o1.w);
                    out_b16[r * 64 + lane]      = p0;
                    out_b16[r * 64 + 32 + lane] = p1;
                }
            }
        }
    }
}

// ---------------- the single mega-kernel ------------------------------------
__global__ __launch_bounds__(NT, 1) void mega_kernel(
    const float* __restrict__ x, const int* __restrict__ ddb,
    const int* __restrict__ src, const int* __restrict__ dst,
    const int* __restrict__ nodes, const int* __restrict__ avgix,
    const float* __restrict__ W1, const float* __restrict__ b1,
    const float* __restrict__ W2, const float* __restrict__ b2,
    float* __restrict__ out)
{
    extern __shared__ float smem[];
    float* A  = smem;                  // 64 * 264 floats
    float* Bs = smem + 64 * ASTR;      // 16 * 256 floats
    __shared__ unsigned s_gen0;
    __shared__ int s_tile;

    const int tid  = threadIdx.x;
    const int lane = tid & 31;
    const int wid  = tid >> 5;
    const int gtid = blockIdx.x * NT + tid;
    const int gs   = NB * NT;

    if (tid == 0) s_gen0 = *(volatile unsigned*)&g_gen;
    __syncthreads();
    const unsigned gen0 = s_gen0;

    // ---- P0: x -> bf16, degree histogram, drug boundaries, counter reset ----
    {
        const float2* x2 = (const float2*)x;
        for (int i = gtid; i < NP * 128; i += gs) {
            float2 v = x2[i];
            g_xb[i] = pack2(v.x, v.y);
        }
    }
    for (int e = gtid; e < E_SG; e += gs)
        atomicAdd(&g_deg[dst[e]], 1);
    if (gtid < 2) g_tctr[gtid] = 0;
    if (gtid <= ND) {
        if (gtid == ND) g_drug_start[ND] = N_SG;
        else {
            int lo = 0, hi = N_SG;
            while (lo < hi) {
                int mid = (lo + hi) >> 1;
                if (avgix[mid] < gtid) lo = mid + 1; else hi = mid;
            }
            g_drug_start[gtid] = lo;
        }
    }
    gridbar(gen0, 1);

    // ---- P1a: per-block chunk sums ----
    int* si = (int*)A;
    {
        int n0  = blockIdx.x * CHUNK;
        int len = NP - n0; if (len > CHUNK) len = CHUNK; if (len < 0) len = 0;
        int v = (tid < len) ? g_deg[n0 + tid] : 0;
        if (tid < CHUNK) si[tid] = v;
        __syncthreads();
        if (tid == 0) {
            int s = 0;
            for (int i = 0; i < len; i++) s += si[i];
            g_part[blockIdx.x] = s;
        }
    }
    gridbar(gen0, 2);

    // ---- P1b: block 0 scans the 148 partials ----
    if (blockIdx.x == 0) {
        int pv = (tid < NB) ? g_part[tid] : 0;
        if (tid < NB) si[tid] = pv;
        __syncthreads();
        if (tid == 0) {
            int run = 0;
            for (int i = 0; i < NB; i++) { int t = si[i]; si[i] = run; run += t; }
        }
        __syncthreads();
        if (tid < NB) g_poff[tid] = si[tid];
    }
    gridbar(gen0, 3);

    // ---- P1c: per-chunk prefix -> rowstart/fill/dinv ----
    {
        int n0  = blockIdx.x * CHUNK;
        int len = NP - n0; if (len > CHUNK) len = CHUNK; if (len < 0) len = 0;
        int v = (tid < len) ? g_deg[n0 + tid] : 0;
        if (tid < CHUNK) si[tid] = v;
        __syncthreads();
        if (tid == 0) {
            int run = g_poff[blockIdx.x];
            for (int i = 0; i < len; i++) { int t = si[i]; si[i] = run; run += t; }
        }
        __syncthreads();
        if (tid < len) {
            int node = n0 + tid;
            int rs = si[tid];
            g_rowstart[node] = rs;
            g_fill[node]     = rs;
            g_dinv[node]     = rsqrtf((float)v + 1.0f);
        }
        if (blockIdx.x == 0 && tid == 0) g_rowstart[NP] = E_SG;
    }
    gridbar(gen0, 4);

    // ---- P2: CSR fill + reset g_deg for next replay ----
    for (int e = gtid; e < E_SG; e += gs) {
        int d   = dst[e];
        int pos = atomicAdd(&g_fill[d], 1);
        g_csr_src[pos] = src[e];
    }
    for (int i = gtid; i < NP; i += gs) g_deg[i] = 0;
    gridbar(gen0, 5);

    // ---- P3: layer 1  h1 = relu(agg(xb) @ W1 + b1) -> fp32 + bf16 ----
    layer_phase((const uint4*)g_xb, W1, b1, nullptr,
                (float4*)g_h1, (uint2*)g_h1b, true, 0, A, Bs, &s_tile);
    gridbar(gen0, 6);

    // ---- P4: layer 2  h2 = agg(h1b) @ W2 + b2 + h1 -> bf16 only ----
    layer_phase((const uint4*)g_h1b, W2, b2, (const float4*)g_h1,
                nullptr, (uint2*)g_h2b, false, 1, A, Bs, &s_tile);
    gridbar(gen0, 7);

    // ---- P5: scatter-mean pooling from bf16 h2 ----
    {
        const uint4* h2b = (const uint4*)g_h2b;
        for (int d = blockIdx.x; d < ND; d += NB) {
            int beg = g_drug_start[d];
            int end = g_drug_start[d + 1];
            float a[8] = {0.f, 0.f, 0.f, 0.f, 0.f, 0.f, 0.f, 0.f};
            for (int base = beg + wid * 32; base < end; base += NT) {
                int m = min(32, end - base);
                int nidx = 0;
                if (lane < m) nidx = nodes[base + lane] * 32;
                int k = 0;
                for (; k + 2 <= m; k += 2) {
                    int i0 = __shfl_sync(0xffffffffu, nidx, k);
                    int i1 = __shfl_sync(0xffffffffu, nidx, k + 1);
                    uint4 u0 = h2b[i0 + lane];
                    uint4 u1 = h2b[i1 + lane];
                    acc_row(a, u0, 1.0f);
                    acc_row(a, u1, 1.0f);
                }
                if (k < m) {
                    int i0 = __shfl_sync(0xffffffffu, nidx, k);
                    uint4 u0 = h2b[i0 + lane];
                    acc_row(a, u0, 1.0f);
                }
            }
            __syncthreads();
            float* P = A;   // 16 warps x 256 floats
            *(float4*)&P[wid * 256 + lane * 8]     = make_float4(a[0], a[1], a[2], a[3]);
            *(float4*)&P[wid * 256 + lane * 8 + 4] = make_float4(a[4], a[5], a[6], a[7]);
            __syncthreads();
            if (tid < 256) {
                float s = 0.f;
                #pragma unroll
                for (int w = 0; w < NWARP; w++) s += P[w * 256 + tid];
                float inv = 1.0f / fmaxf((float)(end - beg), 1.0f);
                g_drug[d * 256 + tid] = s * inv;
            }
            __syncthreads();
        }
    }
    gridbar(gen0, 8);

    // ---- P6: prediction head ----
    {
        const float4* gd = (const float4*)g_drug;
        for (int p = blockIdx.x * NWARP + wid; p < B_DD; p += NB * NWARP) {
            int a = ddb[p];
            int b = ddb[B_DD + p];
            float4 va0 = gd[a * 64 + lane], va1 = gd[a * 64 + 32 + lane];
            float4 vb0 = gd[b * 64 + lane], vb1 = gd[b * 64 + 32 + lane];
            float s = va0.x * vb0.x + va0.y * vb0.y + va0.z * vb0.z + va0.w * vb0.w
                    + va1.x * vb1.x + va1.y * vb1.y + va1.z * vb1.z + va1.w * vb1.w;
            #pragma unroll
            for (int off = 16; off; off >>= 1)
                s += __shfl_down_sync(0xffffffffu, s, off);
            if (lane == 0) out[p] = s;
        }
    }
}

// ---------------- launch ----------------------------------------------------
extern "C" void kernel_launch(void* const* d_in, const int* in_sizes, int n_in,
                              void* d_out, int out_size) {
    const float* x     = (const float*)d_in[0];
    const int*   ddb   = (const int*)d_in[1];
    const int*   sg_ei = (const int*)d_in[4];
    const int*   nodes = (const int*)d_in[5];
    const int*   avgix = (const int*)d_in[6];
    const float* W1    = (const float*)d_in[7];
    const float* b1    = (const float*)d_in[8];
    const float* W2    = (const float*)d_in[9];
    const float* b2    = (const float*)d_in[10];
    float* out = (float*)d_out;

    const int smem_bytes = (64 * ASTR + 16 * 256) * (int)sizeof(float);  // 83968
    static bool attr_set = false;
    if (!attr_set) {
        cudaFuncSetAttribute(mega_kernel, cudaFuncAttributeMaxDynamicSharedMemorySize,
                             smem_bytes);
        attr_set = true;
    }

    mega_kernel<<<NB, NT, smem_bytes>>>(x, ddb, sg_ei, sg_ei + E_SG,
                                        nodes, avgix, W1, b1, W2, b2, out);
}